// round 15
// baseline (speedup 1.0000x reference)
#include <cuda_runtime.h>
#include <cuda_bf16.h>
#include <cuda_fp16.h>
#include <math.h>
#include <stdint.h>

#define B_    8
#define C_    256
#define H_    64
#define W_    64
#define M_    32768
#define NH_   8
#define HD_   32

// ---------------------------------------------------------------------------
// Scratch buffers (__device__ globals: allocation-free)
// ---------------------------------------------------------------------------
__device__ __half g_q  [M_*C_];
__device__ __half g_k  [M_*C_];
__device__ __half g_v  [M_*C_];
__device__ float  g_gate[M_*C_];

__device__ __nv_bfloat16 g_yh [M_*C_],  g_yl [M_*C_];
__device__ __nv_bfloat16 g_chh[M_*C_];                 // single-precision path
__device__ __nv_bfloat16 g_th [M_*128];
__device__ __nv_bfloat16 g_ath[M_*C_],  g_atl[M_*C_];
__device__ __nv_bfloat16 g_wqh[1024*256], g_wql[1024*256];
__device__ __nv_bfloat16 g_w1h[128*256];
__device__ __nv_bfloat16 g_w2h[256*128];
__device__ __nv_bfloat16 g_wph[256*256],  g_wpl[256*256];

// id -> {A_hi, A_lo, B_hi, B_lo} selection (lo may be unused for PROD=1)
__device__ __forceinline__ const __nv_bfloat16* bf_buf(int id) {
    switch (id) {
        case 0:  return g_yh;  case 1:  return g_yl;
        case 2:  return g_chh;
        case 4:  return g_th;
        case 6:  return g_ath; case 7:  return g_atl;
        case 8:  return g_wqh; case 9:  return g_wql;
        case 10: return g_w1h;
        case 12: return g_w2h;
        case 14: return g_wph; case 15: return g_wpl;
    }
    return nullptr;
}

__device__ __forceinline__ void split_bf16(float v, __nv_bfloat16& h, __nv_bfloat16& l) {
    h = __float2bfloat16(v);
    l = __float2bfloat16(v - __bfloat162float(h));
}

// ---------------------------------------------------------------------------
// sm_80-compatible async-copy / ldmatrix / mma.sync helpers
// ---------------------------------------------------------------------------
__device__ __forceinline__ uint32_t smem_to_u32(const void* p) {
    uint32_t a;
    asm("{ .reg .u64 t; cvta.to.shared.u64 t, %1; cvt.u32.u64 %0, t; }"
        : "=r"(a) : "l"(p));
    return a;
}
__device__ __forceinline__ void cp_async16(uint32_t sa, const void* g) {
    asm volatile("cp.async.cg.shared.global [%0], [%1], 16;" :: "r"(sa), "l"(g));
}
#define CP_COMMIT() asm volatile("cp.async.commit_group;" ::: "memory")
#define CP_WAIT(n)  asm volatile("cp.async.wait_group %0;" :: "n"(n) : "memory")

__device__ __forceinline__ void ldsm4(uint32_t* r, uint32_t a) {
    asm volatile("ldmatrix.sync.aligned.m8n8.x4.shared.b16 {%0,%1,%2,%3}, [%4];"
        : "=r"(r[0]), "=r"(r[1]), "=r"(r[2]), "=r"(r[3]) : "r"(a));
}
__device__ __forceinline__ void mma16816(float* c, const uint32_t* a,
                                         uint32_t b0, uint32_t b1) {
    asm volatile(
        "mma.sync.aligned.m16n8k16.row.col.f32.bf16.bf16.f32 "
        "{%0,%1,%2,%3}, {%4,%5,%6,%7}, {%8,%9}, {%0,%1,%2,%3};"
        : "+f"(c[0]), "+f"(c[1]), "+f"(c[2]), "+f"(c[3])
        : "r"(a[0]), "r"(a[1]), "r"(a[2]), "r"(a[3]), "r"(b0), "r"(b1));
}

// Swizzled tile layout: [128 rows][32 bf16] = 64B/row = 4 chunks of 16B.
__device__ __forceinline__ uint32_t sw_off(int row, int c) {
    return (uint32_t)((row * 4 + (c ^ ((row >> 1) & 3))) << 4);
}

// ---------------------------------------------------------------------------
// Kernel 1: 3x3 avg pool + transpose to [pos, C], output split into bf16 hi/lo
// ---------------------------------------------------------------------------
__global__ void __launch_bounds__(256) avgpool_kernel(const float* __restrict__ x)
{
    const int h  = blockIdx.x;
    const int c0 = blockIdx.y * 32;
    const int b  = blockIdx.z;
    __shared__ float s[96][65];

    const int t = threadIdx.x;
    #pragma unroll 4
    for (int ri = 0; ri < 24; ri++) {
        int rowid = ri * 4 + (t >> 6);
        int w  = t & 63;
        int cc = rowid / 3;
        int dh = rowid - cc * 3;
        int hh = h + dh - 1;
        float v = 0.f;
        if (hh >= 0 && hh < H_)
            v = x[(((size_t)b * C_ + c0 + cc) * H_ + hh) * W_ + w];
        s[rowid][w] = v;
    }
    __syncthreads();

    const int cc = t & 31;
    const int wq = t >> 5;
    #pragma unroll
    for (int wi = 0; wi < 8; wi++) {
        int w = wi * 8 + wq;
        float sum = 0.f;
        #pragma unroll
        for (int dh = 0; dh < 3; dh++) {
            const float* row = s[cc * 3 + dh];
            #pragma unroll
            for (int dw = -1; dw <= 1; dw++) {
                int w2 = w + dw;
                if (w2 >= 0 && w2 < W_) sum += row[w2];
            }
        }
        size_t pos = (size_t)b * 4096 + h * 64 + w;
        __nv_bfloat16 hi, lo;
        split_bf16(sum * (1.f / 9.f), hi, lo);
        g_yh[pos * C_ + c0 + cc] = hi;
        g_yl[pos * C_ + c0 + cc] = lo;
    }
}

// ---------------------------------------------------------------------------
// Kernel: weight conversion (QKV/proj hi+lo; gate weights hi only)
// ---------------------------------------------------------------------------
__global__ void __launch_bounds__(256) convert_weights(
    const float* __restrict__ Wq, const float* __restrict__ W1,
    const float* __restrict__ W2, const float* __restrict__ Wp)
{
    int i = blockIdx.x * 256 + threadIdx.x;
    if (i < 262144) {
        int n = i >> 8, kk = i & 255;
        int orig = (n & 255) * 4 + (n >> 8);
        split_bf16(Wq[orig * 256 + kk], g_wqh[i], g_wql[i]);
    } else if (i < 294912) {
        int j = i - 262144;
        g_w1h[j] = __float2bfloat16(W1[j]);
    } else if (i < 327680) {
        int j = i - 294912;
        g_w2h[j] = __float2bfloat16(W2[j]);
    } else if (i < 393216) {
        int j = i - 327680;
        split_bf16(Wp[j], g_wph[j], g_wpl[j]);
    }
}

// ---------------------------------------------------------------------------
// mma.sync bf16 GEMM, PROD = 3 (hi/lo precision split) or 1 (plain bf16).
// C[M,N] = A[M,K] @ W[N,K]^T, fp32 accum.  BM=BN=128, BK=32, 256 threads.
// 3-stage cp.async pipeline, swizzled tiles, one __syncthreads per stage.
// PROD==3 stage: Ah|Al|Bh|Bl (32KB). PROD==1 stage: Ah|Bh (16KB).
// EPI==0 (QKV): blocks with n0>=768 (the `chans` quarter) run single-product
// at runtime — the gate path is provably insensitive to bf16 rounding.
// EPI: 0 QKV split (q/k/v fp16 + ch bf16)  1 relu->bf16 (t)
//      2 sigmoid->gate                      3 bias+NCHW store
// ---------------------------------------------------------------------------
#define TILE_B   8192           // 128 rows * 64B swizzled

template<int EPI, int AID, int BID, int KMAT, int PROD>
__global__ void __launch_bounds__(256, 2) mma_gemm(
    const float* __restrict__ bias, float* __restrict__ outp)
{
    extern __shared__ char sm[];
    const uint32_t smb = smem_to_u32(sm);
    const int t = threadIdx.x;
    const int wid = t >> 5, lane = t & 31;
    const int wm = wid & 3, wn = wid >> 2;
    const int m0 = blockIdx.y * 128;
    const int n0 = blockIdx.x * 128;
    constexpr int S = KMAT / 32;
    constexpr int NTILES  = (PROD == 3) ? 4 : 2;
    constexpr int STAGE_B = NTILES * TILE_B;
    constexpr int BSLOT   = (PROD == 3) ? 2 : 1;

    // runtime precision flag (uniform per block)
    const bool full = (EPI == 0) ? (n0 < 768) : (PROD == 3);

    const __nv_bfloat16* src[4] = { bf_buf(AID), bf_buf(AID + 1),
                                    bf_buf(BID), bf_buf(BID + 1) };

    float acc[2][8][4];
    #pragma unroll
    for (int i = 0; i < 2; i++)
        #pragma unroll
        for (int j = 0; j < 8; j++)
            #pragma unroll
            for (int q = 0; q < 4; q++) acc[i][j][q] = 0.f;

    const int ar = lane & 15;
    const int ahc = lane >> 4;
    const int br = (lane & 7) + ((lane >> 4) << 3);
    const int bhc = (lane >> 3) & 1;

    auto load_stage = [&](int s) {
        const uint32_t sb = smb + (uint32_t)(s % 3) * STAGE_B;
        const int k0 = s * 32;
        #pragma unroll
        for (int tile = 0; tile < NTILES; tile++) {
            if (PROD == 3 && EPI == 0 && !full && (tile & 1)) continue; // skip lo
            const __nv_bfloat16* sp = (PROD == 3) ? src[tile]
                                                  : src[tile * 2];
            const int rb = (PROD == 3) ? ((tile < 2) ? m0 : n0)
                                       : ((tile == 0) ? m0 : n0);
            #pragma unroll
            for (int i = 0; i < 2; i++) {
                int chunk = i * 256 + t;
                int row = chunk >> 2, cc = chunk & 3;
                cp_async16(sb + tile * TILE_B + sw_off(row, cc),
                           sp + (size_t)(rb + row) * KMAT + k0 + cc * 8);
            }
        }
    };

    load_stage(0); CP_COMMIT();
    load_stage(1); CP_COMMIT();
    CP_WAIT(1);
    __syncthreads();

    for (int s = 0; s < S; s++) {
        if (s + 2 < S) load_stage(s + 2);
        CP_COMMIT();

        const uint32_t base = smb + (uint32_t)(s % 3) * STAGE_B;
        const uint32_t bbase = base + BSLOT * TILE_B;
        #pragma unroll
        for (int ks = 0; ks < 2; ks++) {
            uint32_t ah[2][4], al[2][4];
            #pragma unroll
            for (int mt = 0; mt < 2; mt++) {
                uint32_t off = sw_off(wm * 32 + mt * 16 + ar, ks * 2 + ahc);
                ldsm4(ah[mt], base + off);
                if (PROD == 3 && full) ldsm4(al[mt], base + TILE_B + off);
            }
            uint32_t bh[16], bl[16];
            #pragma unroll
            for (int p = 0; p < 4; p++) {
                uint32_t off = sw_off(wn * 64 + p * 16 + br, ks * 2 + bhc);
                ldsm4(&bh[p * 4], bbase + off);
                if (PROD == 3 && full) ldsm4(&bl[p * 4], bbase + TILE_B + off);
            }
            #pragma unroll
            for (int mt = 0; mt < 2; mt++)
                #pragma unroll
                for (int nt = 0; nt < 8; nt++) {
                    const int bi = (nt >> 1) * 4 + (nt & 1) * 2;
                    mma16816(acc[mt][nt], ah[mt], bh[bi], bh[bi + 1]);
                    if (PROD == 3 && full) {
                        mma16816(acc[mt][nt], ah[mt], bl[bi], bl[bi + 1]);
                        mma16816(acc[mt][nt], al[mt], bh[bi], bh[bi + 1]);
                    }
                }
        }

        CP_WAIT(1);
        __syncthreads();
    }

    // ------------------------- epilogue -------------------------
    const int mrow = m0 + wm * 32 + (lane >> 2);
    const int ncol = wn * 64 + (lane & 3) * 2;

    if (EPI == 0) {
        const int g = n0 >> 8;
        #pragma unroll
        for (int mt = 0; mt < 2; mt++) {
            #pragma unroll
            for (int nt = 0; nt < 8; nt++) {
                const int m  = mrow + mt * 16;
                const int ch = ((n0 + ncol) & 255) + nt * 8;
                float v0 = acc[mt][nt][0] + bias[(ch + 0) * 4 + g];
                float v1 = acc[mt][nt][1] + bias[(ch + 1) * 4 + g];
                float v2 = acc[mt][nt][2] + bias[(ch + 0) * 4 + g];
                float v3 = acc[mt][nt][3] + bias[(ch + 1) * 4 + g];
                if (g < 3) {
                    __half* dst = (g == 0) ? g_q : (g == 1) ? g_k : g_v;
                    *(__half2*)&dst[(size_t)m * 256 + ch]       = __floats2half2_rn(v0, v1);
                    *(__half2*)&dst[(size_t)(m + 8) * 256 + ch] = __floats2half2_rn(v2, v3);
                } else {
                    *(__nv_bfloat162*)&g_chh[(size_t)m * 256 + ch] =
                        __nv_bfloat162(__float2bfloat16(v0), __float2bfloat16(v1));
                    *(__nv_bfloat162*)&g_chh[(size_t)(m + 8) * 256 + ch] =
                        __nv_bfloat162(__float2bfloat16(v2), __float2bfloat16(v3));
                }
            }
        }
    } else if (EPI == 1) {
        #pragma unroll
        for (int mt = 0; mt < 2; mt++)
            #pragma unroll
            for (int nt = 0; nt < 8; nt++) {
                const int m = mrow + mt * 16;
                const int n = ncol + nt * 8;          // N = 128, n0 = 0
                float v0 = fmaxf(acc[mt][nt][0] + bias[n],     0.f);
                float v1 = fmaxf(acc[mt][nt][1] + bias[n + 1], 0.f);
                float v2 = fmaxf(acc[mt][nt][2] + bias[n],     0.f);
                float v3 = fmaxf(acc[mt][nt][3] + bias[n + 1], 0.f);
                *(__nv_bfloat162*)&g_th[(size_t)m * 128 + n] =
                    __nv_bfloat162(__float2bfloat16(v0), __float2bfloat16(v1));
                *(__nv_bfloat162*)&g_th[(size_t)(m + 8) * 128 + n] =
                    __nv_bfloat162(__float2bfloat16(v2), __float2bfloat16(v3));
            }
    } else if (EPI == 2) {
        #pragma unroll
        for (int mt = 0; mt < 2; mt++)
            #pragma unroll
            for (int nt = 0; nt < 8; nt++) {
                const int m = mrow + mt * 16;
                const int n = n0 + ncol + nt * 8;
                float v0 = 1.f / (1.f + expf(-(acc[mt][nt][0] + bias[n])));
                float v1 = 1.f / (1.f + expf(-(acc[mt][nt][1] + bias[n + 1])));
                float v2 = 1.f / (1.f + expf(-(acc[mt][nt][2] + bias[n])));
                float v3 = 1.f / (1.f + expf(-(acc[mt][nt][3] + bias[n + 1])));
                *(float2*)&g_gate[(size_t)m * 256 + n]       = make_float2(v0, v1);
                *(float2*)&g_gate[(size_t)(m + 8) * 256 + n] = make_float2(v2, v3);
            }
    } else { // EPI == 3: bias + smem transpose + coalesced NCHW store
        float* smT = (float*)sm;                  // [128 n][stride 132 m]
        const int ml = mrow - m0;
        #pragma unroll
        for (int mt = 0; mt < 2; mt++)
            #pragma unroll
            for (int nt = 0; nt < 8; nt++) {
                const int n = ncol + nt * 8;      // local n (0..127)
                smT[(n)     * 132 + ml + mt * 16]     = acc[mt][nt][0] + bias[n0 + n];
                smT[(n + 1) * 132 + ml + mt * 16]     = acc[mt][nt][1] + bias[n0 + n + 1];
                smT[(n)     * 132 + ml + mt * 16 + 8] = acc[mt][nt][2] + bias[n0 + n];
                smT[(n + 1) * 132 + ml + mt * 16 + 8] = acc[mt][nt][3] + bias[n0 + n + 1];
            }
        __syncthreads();
        const int nl = t >> 1, half = t & 1;
        const int bi = m0 >> 12, hw0 = m0 & 4095;
        float* orow = outp + ((size_t)(bi * 256 + n0 + nl)) * 4096 + hw0 + half * 64;
        #pragma unroll
        for (int i = 0; i < 16; i++)
            *(float4*)&orow[i * 4] = *(float4*)&smT[nl * 132 + half * 64 + i * 4];
    }
}

// ---------------------------------------------------------------------------
// Kernel: 3x3 local-window attention + gate; q/k/v fp16, writes bf16 hi/lo
// ---------------------------------------------------------------------------
__global__ void __launch_bounds__(256) attn_kernel()
{
    const int pos  = blockIdx.x;
    const int head = threadIdx.x >> 5;
    const int lane = threadIdx.x & 31;
    const int hw = pos & 4095;
    const int iy = hw >> 6, ix = hw & 63;
    const int ch = head * HD_ + lane;
    const size_t base = (size_t)pos * C_ + ch;

    const float q = __half2float(g_q[base]);
    float logit[9], vv[9];
    #pragma unroll
    for (int j = 0; j < 9; j++) {
        int dy = j / 3 - 1, dx = j % 3 - 1;
        int ny = iy + dy, nx = ix + dx;
        float p = 0.f, val = 0.f;
        if (ny >= 0 && ny < H_ && nx >= 0 && nx < W_) {
            int npos = pos + dy * 64 + dx;
            size_t nb = (size_t)npos * C_ + ch;
            p   = q * __half2float(g_k[nb]);
            val = __half2float(g_v[nb]);
        }
        #pragma unroll
        for (int off = 16; off; off >>= 1)
            p += __shfl_xor_sync(0xffffffffu, p, off);
        logit[j] = p * 0.17677669529663687f;
        vv[j] = val;
    }

    float mx = logit[0];
    #pragma unroll
    for (int j = 1; j < 9; j++) mx = fmaxf(mx, logit[j]);
    float e[9], ssum = 0.f;
    #pragma unroll
    for (int j = 0; j < 9; j++) { e[j] = __expf(logit[j] - mx); ssum += e[j]; }
    const float inv = 1.f / ssum;
    float o = 0.f;
    #pragma unroll
    for (int j = 0; j < 9; j++) o += e[j] * inv * vv[j];

    const float r = o * (1.f + g_gate[base]);
    __nv_bfloat16 hi, lo;
    split_bf16(r, hi, lo);
    g_ath[base] = hi;
    g_atl[base] = lo;
}

// ---------------------------------------------------------------------------
extern "C" void kernel_launch(void* const* d_in, const int* in_sizes, int n_in,
                              void* d_out, int out_size)
{
    const float* x     = (const float*)d_in[0];
    const float* W_qkv = (const float*)d_in[1];
    const float* b_qkv = (const float*)d_in[2];
    const float* W1    = (const float*)d_in[3];
    const float* b1    = (const float*)d_in[4];
    const float* W2    = (const float*)d_in[5];
    const float* b2    = (const float*)d_in[6];
    const float* Wp    = (const float*)d_in[7];
    const float* bp    = (const float*)d_in[8];
    float* out = (float*)d_out;

    const int SMEM3 = 3 * 4 * TILE_B;   // 96 KB (PROD=3)
    const int SMEM1 = 3 * 2 * TILE_B;   // 48 KB (PROD=1)

    cudaFuncSetAttribute(mma_gemm<0, 0,  8, 256, 3>, cudaFuncAttributeMaxDynamicSharedMemorySize, SMEM3);
    cudaFuncSetAttribute(mma_gemm<1, 2, 10, 256, 1>, cudaFuncAttributeMaxDynamicSharedMemorySize, SMEM1);
    cudaFuncSetAttribute(mma_gemm<2, 4, 12, 128, 1>, cudaFuncAttributeMaxDynamicSharedMemorySize, SMEM1);
    cudaFuncSetAttribute(mma_gemm<3, 6, 14, 256, 3>, cudaFuncAttributeMaxDynamicSharedMemorySize, SMEM3);

    // 1) weight conversion + avg pool
    convert_weights<<<1536, 256>>>(W_qkv, W1, W2, Wp);
    avgpool_kernel<<<dim3(H_, C_ / 32, B_), 256>>>(x);

    // 2) QKV GEMM: [32768,1024] = y @ Wqkv^T  -> q/k/v fp16, ch bf16
    //    (ch blocks n0>=768 run single-product)
    mma_gemm<0, 0, 8, 256, 3><<<dim3(8, 256), 256, SMEM3>>>(b_qkv, nullptr);

    // 3) gate hidden: relu(ch @ W1^T + b1) -> t bf16  (N=128, single product)
    mma_gemm<1, 2, 10, 256, 1><<<dim3(1, 256), 256, SMEM1>>>(b1, nullptr);

    // 4) gate: sigmoid(t @ W2^T + b2) -> g_gate  (N=256, K=128, single product)
    mma_gemm<2, 4, 12, 128, 1><<<dim3(2, 256), 256, SMEM1>>>(b2, nullptr);

    // 5) local attention + (1+g) -> ath/atl bf16
    attn_kernel<<<M_, 256>>>();

    // 6) projection + bias + NCHW store -> d_out
    mma_gemm<3, 6, 14, 256, 3><<<dim3(2, 256), 256, SMEM3>>>(bp, out);
}

// round 16
// speedup vs baseline: 1.0022x; 1.0022x over previous
#include <cuda_runtime.h>
#include <cuda_bf16.h>
#include <cuda_fp16.h>
#include <math.h>
#include <stdint.h>

#define B_    8
#define C_    256
#define H_    64
#define W_    64
#define M_    32768
#define NH_   8
#define HD_   32

// ---------------------------------------------------------------------------
// Scratch buffers (__device__ globals: allocation-free)
// ---------------------------------------------------------------------------
__device__ __half g_q  [M_*C_];
__device__ __half g_k  [M_*C_];
__device__ __half g_v  [M_*C_];
__device__ float  g_gate[M_*C_];

__device__ __nv_bfloat16 g_yh [M_*C_],  g_yl [M_*C_];
__device__ __nv_bfloat16 g_chh[M_*C_];                 // single-precision path
__device__ __nv_bfloat16 g_th [M_*128];
__device__ __nv_bfloat16 g_ath[M_*C_],  g_atl[M_*C_];
__device__ __nv_bfloat16 g_wqh[1024*256], g_wql[1024*256];
__device__ __nv_bfloat16 g_w1h[128*256];
__device__ __nv_bfloat16 g_w2h[256*128];
__device__ __nv_bfloat16 g_wph[256*256],  g_wpl[256*256];

// id -> {A_hi, A_lo, B_hi, B_lo} selection (lo may be unused for PROD=1)
__device__ __forceinline__ const __nv_bfloat16* bf_buf(int id) {
    switch (id) {
        case 0:  return g_yh;  case 1:  return g_yl;
        case 2:  return g_chh;
        case 4:  return g_th;
        case 6:  return g_ath; case 7:  return g_atl;
        case 8:  return g_wqh; case 9:  return g_wql;
        case 10: return g_w1h;
        case 12: return g_w2h;
        case 14: return g_wph; case 15: return g_wpl;
    }
    return nullptr;
}

__device__ __forceinline__ void split_bf16(float v, __nv_bfloat16& h, __nv_bfloat16& l) {
    h = __float2bfloat16(v);
    l = __float2bfloat16(v - __bfloat162float(h));
}

// ---------------------------------------------------------------------------
// sm_80-compatible async-copy / ldmatrix / mma.sync helpers
// ---------------------------------------------------------------------------
__device__ __forceinline__ uint32_t smem_to_u32(const void* p) {
    uint32_t a;
    asm("{ .reg .u64 t; cvta.to.shared.u64 t, %1; cvt.u32.u64 %0, t; }"
        : "=r"(a) : "l"(p));
    return a;
}
__device__ __forceinline__ void cp_async16(uint32_t sa, const void* g) {
    asm volatile("cp.async.cg.shared.global [%0], [%1], 16;" :: "r"(sa), "l"(g));
}
#define CP_COMMIT() asm volatile("cp.async.commit_group;" ::: "memory")
#define CP_WAIT(n)  asm volatile("cp.async.wait_group %0;" :: "n"(n) : "memory")

__device__ __forceinline__ void ldsm4(uint32_t* r, uint32_t a) {
    asm volatile("ldmatrix.sync.aligned.m8n8.x4.shared.b16 {%0,%1,%2,%3}, [%4];"
        : "=r"(r[0]), "=r"(r[1]), "=r"(r[2]), "=r"(r[3]) : "r"(a));
}
__device__ __forceinline__ void mma16816(float* c, const uint32_t* a,
                                         uint32_t b0, uint32_t b1) {
    asm volatile(
        "mma.sync.aligned.m16n8k16.row.col.f32.bf16.bf16.f32 "
        "{%0,%1,%2,%3}, {%4,%5,%6,%7}, {%8,%9}, {%0,%1,%2,%3};"
        : "+f"(c[0]), "+f"(c[1]), "+f"(c[2]), "+f"(c[3])
        : "r"(a[0]), "r"(a[1]), "r"(a[2]), "r"(a[3]), "r"(b0), "r"(b1));
}

// Swizzled tile layout: [128 rows][32 bf16] = 64B/row = 4 chunks of 16B.
__device__ __forceinline__ uint32_t sw_off(int row, int c) {
    return (uint32_t)((row * 4 + (c ^ ((row >> 1) & 3))) << 4);
}

// ---------------------------------------------------------------------------
// Kernel 1: 3x3 avg pool + transpose to [pos, C], output split into bf16 hi/lo
// ---------------------------------------------------------------------------
__global__ void __launch_bounds__(256) avgpool_kernel(const float* __restrict__ x)
{
    const int h  = blockIdx.x;
    const int c0 = blockIdx.y * 32;
    const int b  = blockIdx.z;
    __shared__ float s[96][65];

    const int t = threadIdx.x;
    #pragma unroll 4
    for (int ri = 0; ri < 24; ri++) {
        int rowid = ri * 4 + (t >> 6);
        int w  = t & 63;
        int cc = rowid / 3;
        int dh = rowid - cc * 3;
        int hh = h + dh - 1;
        float v = 0.f;
        if (hh >= 0 && hh < H_)
            v = x[(((size_t)b * C_ + c0 + cc) * H_ + hh) * W_ + w];
        s[rowid][w] = v;
    }
    __syncthreads();

    const int cc = t & 31;
    const int wq = t >> 5;
    #pragma unroll
    for (int wi = 0; wi < 8; wi++) {
        int w = wi * 8 + wq;
        float sum = 0.f;
        #pragma unroll
        for (int dh = 0; dh < 3; dh++) {
            const float* row = s[cc * 3 + dh];
            #pragma unroll
            for (int dw = -1; dw <= 1; dw++) {
                int w2 = w + dw;
                if (w2 >= 0 && w2 < W_) sum += row[w2];
            }
        }
        size_t pos = (size_t)b * 4096 + h * 64 + w;
        __nv_bfloat16 hi, lo;
        split_bf16(sum * (1.f / 9.f), hi, lo);
        g_yh[pos * C_ + c0 + cc] = hi;
        g_yl[pos * C_ + c0 + cc] = lo;
    }
}

// ---------------------------------------------------------------------------
// Kernel: weight conversion (QKV/proj hi+lo; gate weights hi only)
// ---------------------------------------------------------------------------
__global__ void __launch_bounds__(256) convert_weights(
    const float* __restrict__ Wq, const float* __restrict__ W1,
    const float* __restrict__ W2, const float* __restrict__ Wp)
{
    int i = blockIdx.x * 256 + threadIdx.x;
    if (i < 262144) {
        int n = i >> 8, kk = i & 255;
        int orig = (n & 255) * 4 + (n >> 8);
        split_bf16(Wq[orig * 256 + kk], g_wqh[i], g_wql[i]);
    } else if (i < 294912) {
        int j = i - 262144;
        g_w1h[j] = __float2bfloat16(W1[j]);
    } else if (i < 327680) {
        int j = i - 294912;
        g_w2h[j] = __float2bfloat16(W2[j]);
    } else if (i < 393216) {
        int j = i - 327680;
        split_bf16(Wp[j], g_wph[j], g_wpl[j]);
    }
}

// ---------------------------------------------------------------------------
// mma.sync bf16 GEMM, PROD = 3 (hi/lo precision split) or 1 (plain bf16).
// C[M,N] = A[M,K] @ W[N,K]^T, fp32 accum.  BM=BN=128, BK=32, 256 threads.
// 3-stage cp.async pipeline, swizzled tiles, one __syncthreads per stage.
// PROD==3 stage: Ah|Al|Bh|Bl (32KB). PROD==1 stage: Ah|Bh (16KB).
// EPI==0 (QKV): blocks with n0>=768 (the `chans` quarter) run single-product
// at runtime — the gate path is provably insensitive to bf16 rounding.
// EPI: 0 QKV split (q/k/v fp16 + ch bf16)  1 relu->bf16 (t)
//      2 sigmoid->gate                      3 bias+NCHW store
// ---------------------------------------------------------------------------
#define TILE_B   8192           // 128 rows * 64B swizzled

template<int EPI, int AID, int BID, int KMAT, int PROD>
__global__ void __launch_bounds__(256, 2) mma_gemm(
    const float* __restrict__ bias, float* __restrict__ outp)
{
    extern __shared__ char sm[];
    const uint32_t smb = smem_to_u32(sm);
    const int t = threadIdx.x;
    const int wid = t >> 5, lane = t & 31;
    const int wm = wid & 3, wn = wid >> 2;
    const int m0 = blockIdx.y * 128;
    const int n0 = blockIdx.x * 128;
    constexpr int S = KMAT / 32;
    constexpr int NTILES  = (PROD == 3) ? 4 : 2;
    constexpr int STAGE_B = NTILES * TILE_B;
    constexpr int BSLOT   = (PROD == 3) ? 2 : 1;

    // runtime precision flag (uniform per block)
    const bool full = (EPI == 0) ? (n0 < 768) : (PROD == 3);

    const __nv_bfloat16* src[4] = { bf_buf(AID), bf_buf(AID + 1),
                                    bf_buf(BID), bf_buf(BID + 1) };

    float acc[2][8][4];
    #pragma unroll
    for (int i = 0; i < 2; i++)
        #pragma unroll
        for (int j = 0; j < 8; j++)
            #pragma unroll
            for (int q = 0; q < 4; q++) acc[i][j][q] = 0.f;

    const int ar = lane & 15;
    const int ahc = lane >> 4;
    const int br = (lane & 7) + ((lane >> 4) << 3);
    const int bhc = (lane >> 3) & 1;

    auto load_stage = [&](int s) {
        const uint32_t sb = smb + (uint32_t)(s % 3) * STAGE_B;
        const int k0 = s * 32;
        #pragma unroll
        for (int tile = 0; tile < NTILES; tile++) {
            if (PROD == 3 && EPI == 0 && !full && (tile & 1)) continue; // skip lo
            const __nv_bfloat16* sp = (PROD == 3) ? src[tile]
                                                  : src[tile * 2];
            const int rb = (PROD == 3) ? ((tile < 2) ? m0 : n0)
                                       : ((tile == 0) ? m0 : n0);
            #pragma unroll
            for (int i = 0; i < 2; i++) {
                int chunk = i * 256 + t;
                int row = chunk >> 2, cc = chunk & 3;
                cp_async16(sb + tile * TILE_B + sw_off(row, cc),
                           sp + (size_t)(rb + row) * KMAT + k0 + cc * 8);
            }
        }
    };

    load_stage(0); CP_COMMIT();
    load_stage(1); CP_COMMIT();
    CP_WAIT(1);
    __syncthreads();

    for (int s = 0; s < S; s++) {
        if (s + 2 < S) load_stage(s + 2);
        CP_COMMIT();

        const uint32_t base = smb + (uint32_t)(s % 3) * STAGE_B;
        const uint32_t bbase = base + BSLOT * TILE_B;
        #pragma unroll
        for (int ks = 0; ks < 2; ks++) {
            uint32_t ah[2][4], al[2][4];
            #pragma unroll
            for (int mt = 0; mt < 2; mt++) {
                uint32_t off = sw_off(wm * 32 + mt * 16 + ar, ks * 2 + ahc);
                ldsm4(ah[mt], base + off);
                if (PROD == 3 && full) ldsm4(al[mt], base + TILE_B + off);
            }
            uint32_t bh[16], bl[16];
            #pragma unroll
            for (int p = 0; p < 4; p++) {
                uint32_t off = sw_off(wn * 64 + p * 16 + br, ks * 2 + bhc);
                ldsm4(&bh[p * 4], bbase + off);
                if (PROD == 3 && full) ldsm4(&bl[p * 4], bbase + TILE_B + off);
            }
            #pragma unroll
            for (int mt = 0; mt < 2; mt++)
                #pragma unroll
                for (int nt = 0; nt < 8; nt++) {
                    const int bi = (nt >> 1) * 4 + (nt & 1) * 2;
                    mma16816(acc[mt][nt], ah[mt], bh[bi], bh[bi + 1]);
                    if (PROD == 3 && full) {
                        mma16816(acc[mt][nt], ah[mt], bl[bi], bl[bi + 1]);
                        mma16816(acc[mt][nt], al[mt], bh[bi], bh[bi + 1]);
                    }
                }
        }

        CP_WAIT(1);
        __syncthreads();
    }

    // ------------------------- epilogue -------------------------
    const int mrow = m0 + wm * 32 + (lane >> 2);
    const int ncol = wn * 64 + (lane & 3) * 2;

    if (EPI == 0) {
        const int g = n0 >> 8;
        #pragma unroll
        for (int mt = 0; mt < 2; mt++) {
            #pragma unroll
            for (int nt = 0; nt < 8; nt++) {
                const int m  = mrow + mt * 16;
                const int ch = ((n0 + ncol) & 255) + nt * 8;
                float v0 = acc[mt][nt][0] + bias[(ch + 0) * 4 + g];
                float v1 = acc[mt][nt][1] + bias[(ch + 1) * 4 + g];
                float v2 = acc[mt][nt][2] + bias[(ch + 0) * 4 + g];
                float v3 = acc[mt][nt][3] + bias[(ch + 1) * 4 + g];
                if (g < 3) {
                    __half* dst = (g == 0) ? g_q : (g == 1) ? g_k : g_v;
                    *(__half2*)&dst[(size_t)m * 256 + ch]       = __floats2half2_rn(v0, v1);
                    *(__half2*)&dst[(size_t)(m + 8) * 256 + ch] = __floats2half2_rn(v2, v3);
                } else {
                    *(__nv_bfloat162*)&g_chh[(size_t)m * 256 + ch] =
                        __nv_bfloat162(__float2bfloat16(v0), __float2bfloat16(v1));
                    *(__nv_bfloat162*)&g_chh[(size_t)(m + 8) * 256 + ch] =
                        __nv_bfloat162(__float2bfloat16(v2), __float2bfloat16(v3));
                }
            }
        }
    } else if (EPI == 1) {
        #pragma unroll
        for (int mt = 0; mt < 2; mt++)
            #pragma unroll
            for (int nt = 0; nt < 8; nt++) {
                const int m = mrow + mt * 16;
                const int n = ncol + nt * 8;          // N = 128, n0 = 0
                float v0 = fmaxf(acc[mt][nt][0] + bias[n],     0.f);
                float v1 = fmaxf(acc[mt][nt][1] + bias[n + 1], 0.f);
                float v2 = fmaxf(acc[mt][nt][2] + bias[n],     0.f);
                float v3 = fmaxf(acc[mt][nt][3] + bias[n + 1], 0.f);
                *(__nv_bfloat162*)&g_th[(size_t)m * 128 + n] =
                    __nv_bfloat162(__float2bfloat16(v0), __float2bfloat16(v1));
                *(__nv_bfloat162*)&g_th[(size_t)(m + 8) * 128 + n] =
                    __nv_bfloat162(__float2bfloat16(v2), __float2bfloat16(v3));
            }
    } else if (EPI == 2) {
        #pragma unroll
        for (int mt = 0; mt < 2; mt++)
            #pragma unroll
            for (int nt = 0; nt < 8; nt++) {
                const int m = mrow + mt * 16;
                const int n = n0 + ncol + nt * 8;
                float v0 = 1.f / (1.f + expf(-(acc[mt][nt][0] + bias[n])));
                float v1 = 1.f / (1.f + expf(-(acc[mt][nt][1] + bias[n + 1])));
                float v2 = 1.f / (1.f + expf(-(acc[mt][nt][2] + bias[n])));
                float v3 = 1.f / (1.f + expf(-(acc[mt][nt][3] + bias[n + 1])));
                *(float2*)&g_gate[(size_t)m * 256 + n]       = make_float2(v0, v1);
                *(float2*)&g_gate[(size_t)(m + 8) * 256 + n] = make_float2(v2, v3);
            }
    } else { // EPI == 3: bias + smem transpose + coalesced NCHW store
        float* smT = (float*)sm;                  // [128 n][stride 132 m]
        const int ml = mrow - m0;
        #pragma unroll
        for (int mt = 0; mt < 2; mt++)
            #pragma unroll
            for (int nt = 0; nt < 8; nt++) {
                const int n = ncol + nt * 8;      // local n (0..127)
                smT[(n)     * 132 + ml + mt * 16]     = acc[mt][nt][0] + bias[n0 + n];
                smT[(n + 1) * 132 + ml + mt * 16]     = acc[mt][nt][1] + bias[n0 + n + 1];
                smT[(n)     * 132 + ml + mt * 16 + 8] = acc[mt][nt][2] + bias[n0 + n];
                smT[(n + 1) * 132 + ml + mt * 16 + 8] = acc[mt][nt][3] + bias[n0 + n + 1];
            }
        __syncthreads();
        const int nl = t >> 1, half = t & 1;
        const int bi = m0 >> 12, hw0 = m0 & 4095;
        float* orow = outp + ((size_t)(bi * 256 + n0 + nl)) * 4096 + hw0 + half * 64;
        #pragma unroll
        for (int i = 0; i < 16; i++)
            *(float4*)&orow[i * 4] = *(float4*)&smT[nl * 132 + half * 64 + i * 4];
    }
}

// ---------------------------------------------------------------------------
// Kernel: 3x3 local-window attention + gate; q/k/v fp16, writes bf16 hi/lo
// ---------------------------------------------------------------------------
__global__ void __launch_bounds__(256) attn_kernel()
{
    const int pos  = blockIdx.x;
    const int head = threadIdx.x >> 5;
    const int lane = threadIdx.x & 31;
    const int hw = pos & 4095;
    const int iy = hw >> 6, ix = hw & 63;
    const int ch = head * HD_ + lane;
    const size_t base = (size_t)pos * C_ + ch;

    const float q = __half2float(g_q[base]);
    float logit[9], vv[9];
    #pragma unroll
    for (int j = 0; j < 9; j++) {
        int dy = j / 3 - 1, dx = j % 3 - 1;
        int ny = iy + dy, nx = ix + dx;
        float p = 0.f, val = 0.f;
        if (ny >= 0 && ny < H_ && nx >= 0 && nx < W_) {
            int npos = pos + dy * 64 + dx;
            size_t nb = (size_t)npos * C_ + ch;
            p   = q * __half2float(g_k[nb]);
            val = __half2float(g_v[nb]);
        }
        #pragma unroll
        for (int off = 16; off; off >>= 1)
            p += __shfl_xor_sync(0xffffffffu, p, off);
        logit[j] = p * 0.17677669529663687f;
        vv[j] = val;
    }

    float mx = logit[0];
    #pragma unroll
    for (int j = 1; j < 9; j++) mx = fmaxf(mx, logit[j]);
    float e[9], ssum = 0.f;
    #pragma unroll
    for (int j = 0; j < 9; j++) { e[j] = __expf(logit[j] - mx); ssum += e[j]; }
    const float inv = 1.f / ssum;
    float o = 0.f;
    #pragma unroll
    for (int j = 0; j < 9; j++) o += e[j] * inv * vv[j];

    const float r = o * (1.f + g_gate[base]);
    __nv_bfloat16 hi, lo;
    split_bf16(r, hi, lo);
    g_ath[base] = hi;
    g_atl[base] = lo;
}

// ---------------------------------------------------------------------------
extern "C" void kernel_launch(void* const* d_in, const int* in_sizes, int n_in,
                              void* d_out, int out_size)
{
    const float* x     = (const float*)d_in[0];
    const float* W_qkv = (const float*)d_in[1];
    const float* b_qkv = (const float*)d_in[2];
    const float* W1    = (const float*)d_in[3];
    const float* b1    = (const float*)d_in[4];
    const float* W2    = (const float*)d_in[5];
    const float* b2    = (const float*)d_in[6];
    const float* Wp    = (const float*)d_in[7];
    const float* bp    = (const float*)d_in[8];
    float* out = (float*)d_out;

    const int SMEM3 = 3 * 4 * TILE_B;   // 96 KB (PROD=3)
    const int SMEM1 = 3 * 2 * TILE_B;   // 48 KB (PROD=1)

    cudaFuncSetAttribute(mma_gemm<0, 0,  8, 256, 3>, cudaFuncAttributeMaxDynamicSharedMemorySize, SMEM3);
    cudaFuncSetAttribute(mma_gemm<1, 2, 10, 256, 1>, cudaFuncAttributeMaxDynamicSharedMemorySize, SMEM1);
    cudaFuncSetAttribute(mma_gemm<2, 4, 12, 128, 1>, cudaFuncAttributeMaxDynamicSharedMemorySize, SMEM1);
    cudaFuncSetAttribute(mma_gemm<3, 6, 14, 256, 3>, cudaFuncAttributeMaxDynamicSharedMemorySize, SMEM3);

    // 1) weight conversion + avg pool
    convert_weights<<<1536, 256>>>(W_qkv, W1, W2, Wp);
    avgpool_kernel<<<dim3(H_, C_ / 32, B_), 256>>>(x);

    // 2) QKV GEMM: [32768,1024] = y @ Wqkv^T  -> q/k/v fp16, ch bf16
    //    (ch blocks n0>=768 run single-product)
    mma_gemm<0, 0, 8, 256, 3><<<dim3(8, 256), 256, SMEM3>>>(b_qkv, nullptr);

    // 3) gate hidden: relu(ch @ W1^T + b1) -> t bf16  (N=128, single product)
    mma_gemm<1, 2, 10, 256, 1><<<dim3(1, 256), 256, SMEM1>>>(b1, nullptr);

    // 4) gate: sigmoid(t @ W2^T + b2) -> g_gate  (N=256, K=128, single product)
    mma_gemm<2, 4, 12, 128, 1><<<dim3(2, 256), 256, SMEM1>>>(b2, nullptr);

    // 5) local attention + (1+g) -> ath/atl bf16
    attn_kernel<<<M_, 256>>>();

    // 6) projection + bias + NCHW store -> d_out
    mma_gemm<3, 6, 14, 256, 3><<<dim3(2, 256), 256, SMEM3>>>(bp, out);
}